// round 2
// baseline (speedup 1.0000x reference)
#include <cuda_runtime.h>
#include <math.h>

#define BSZ 2
#define SEQ 2048
#define DIM 2048
#define NH 16
#define HD 128
#define M_TOT (BSZ * SEQ)   // 4096

// Scratch: Q, K, V activations and attention output (pre out-proj).
__device__ float g_q[(size_t)M_TOT * DIM];
__device__ float g_k[(size_t)M_TOT * DIM];
__device__ float g_v[(size_t)M_TOT * DIM];
__device__ float g_ao[(size_t)M_TOT * DIM];

// ---------------------------------------------------------------------------
// SGEMM: C[M,N] = A[M,K] @ B[N,K]^T   (both A and B row-major, K contiguous)
// M = 4096, N = K = 2048. Block tile 128x128, K-tile 8, 8x8 per thread.
// ---------------------------------------------------------------------------
__global__ __launch_bounds__(256) void sgemm_nt(const float* __restrict__ A,
                                                const float* __restrict__ B,
                                                float* __restrict__ C) {
    const int K = DIM;
    __shared__ float As[8][128];
    __shared__ float Bs[8][128];
    int t = threadIdx.x;
    int bm = blockIdx.y * 128, bn = blockIdx.x * 128;
    int lr = t >> 1, lk = (t & 1) * 4;      // loader: row 0..127, k-quad 0/4
    int tx = t & 15, ty = t >> 4;           // compute: 16x16 thread grid

    const float* Aptr = A + (size_t)(bm + lr) * K + lk;
    const float* Bptr = B + (size_t)(bn + lr) * K + lk;

    float acc[8][8];
#pragma unroll
    for (int i = 0; i < 8; i++)
#pragma unroll
        for (int j = 0; j < 8; j++) acc[i][j] = 0.f;

    for (int k0 = 0; k0 < K; k0 += 8) {
        float4 a = *(const float4*)(Aptr + k0);
        float4 b = *(const float4*)(Bptr + k0);
        __syncthreads();   // previous iteration's smem reads complete
        As[lk + 0][lr] = a.x; As[lk + 1][lr] = a.y;
        As[lk + 2][lr] = a.z; As[lk + 3][lr] = a.w;
        Bs[lk + 0][lr] = b.x; Bs[lk + 1][lr] = b.y;
        Bs[lk + 2][lr] = b.z; Bs[lk + 3][lr] = b.w;
        __syncthreads();
#pragma unroll
        for (int kk = 0; kk < 8; kk++) {
            float ar[8], br[8];
#pragma unroll
            for (int i = 0; i < 8; i++) ar[i] = As[kk][ty * 8 + i];
#pragma unroll
            for (int j = 0; j < 8; j++) br[j] = Bs[kk][tx * 8 + j];
#pragma unroll
            for (int i = 0; i < 8; i++)
#pragma unroll
                for (int j = 0; j < 8; j++) acc[i][j] += ar[i] * br[j];
        }
    }

#pragma unroll
    for (int i = 0; i < 8; i++) {
        float* Crow = C + (size_t)(bm + ty * 8 + i) * DIM + bn + tx * 8;
#pragma unroll
        for (int j = 0; j < 8; j += 4) {
            float4 v = make_float4(acc[i][j], acc[i][j + 1], acc[i][j + 2], acc[i][j + 3]);
            *(float4*)(Crow + j) = v;
        }
    }
}

// ---------------------------------------------------------------------------
// RoPE on Q and K in-place. Layout [M_TOT, DIM], pair (2i, 2i+1) within head.
// ---------------------------------------------------------------------------
__global__ void rope_kernel(float* __restrict__ q, float* __restrict__ k,
                            const float* __restrict__ cs, const float* __restrict__ sn) {
    int p = blockIdx.x * blockDim.x + threadIdx.x;   // pair index
    const int NP = M_TOT * DIM / 2;
    if (p >= NP) return;
    int row = p / (DIM / 2);
    int pr  = p % (DIM / 2);
    int h = pr / (HD / 2);
    int i = pr % (HD / 2);
    int s = row % SEQ;
    float c  = cs[s * (HD / 2) + i];
    float si = sn[s * (HD / 2) + i];
    size_t off = (size_t)row * DIM + h * HD + 2 * i;
    float2 qv = *(float2*)(q + off);
    float2 kv = *(float2*)(k + off);
    float2 qo = make_float2(qv.x * c - qv.y * si, qv.x * si + qv.y * c);
    float2 ko = make_float2(kv.x * c - kv.y * si, kv.x * si + kv.y * c);
    *(float2*)(q + off) = qo;
    *(float2*)(k + off) = ko;
}

// ---------------------------------------------------------------------------
// Flash attention (fp32, causal). Block = one (b, h, 128-row q-tile).
// 256 threads: thread t owns (row = t/2, half = t&1) -> 64-dim half of q & acc
// in registers. K/V tiles (64x128) streamed through smem; online softmax.
// Score = pairwise shfl-combined dot.
// ---------------------------------------------------------------------------
#define BR 128
#define BC 64
__global__ __launch_bounds__(256) void flash_kernel(const float* __restrict__ Q,
                                                    const float* __restrict__ Kg,
                                                    const float* __restrict__ Vg,
                                                    float* __restrict__ O) {
    __shared__ float Ks[BC][HD];
    __shared__ float Vs[BC][HD];
    int b = blockIdx.z, h = blockIdx.y, q0 = blockIdx.x * BR;
    int t = threadIdx.x;
    int row = t >> 1, half = t & 1;
    int qrow = q0 + row;
    size_t base = (size_t)b * SEQ * DIM + (size_t)h * HD;

    // Load this thread's q half into registers.
    float4 q4[16];
    const float* qptr = Q + base + (size_t)qrow * DIM + half * 64;
#pragma unroll
    for (int i = 0; i < 16; i++) q4[i] = *(const float4*)(qptr + 4 * i);

    float acc[64];
#pragma unroll
    for (int i = 0; i < 64; i++) acc[i] = 0.f;
    float m = -1e30f, l = 0.f;
    const float scale = 0.08838834764831845f;   // 1/sqrt(128)

    int nk = q0 / BC + 2;   // causal: k-tiles with k0 <= q0+127
    for (int kt = 0; kt < nk; kt++) {
        int k0 = kt * BC;
        __syncthreads();
        // Load K,V tile: 64x128 floats = 2048 float4; 8 per thread, coalesced.
#pragma unroll
        for (int i = 0; i < 8; i++) {
            int fl = t + 256 * i;
            int r  = fl >> 5;        // 32 float4 per row
            int c4 = fl & 31;
            size_t g = base + (size_t)(k0 + r) * DIM + c4 * 4;
            *(float4*)&Ks[r][c4 * 4] = *(const float4*)(Kg + g);
            *(float4*)&Vs[r][c4 * 4] = *(const float4*)(Vg + g);
        }
        __syncthreads();

        for (int j = 0; j < BC; j++) {
            float part = 0.f;
#pragma unroll
            for (int i = 0; i < 16; i++) {
                float4 kv = *(const float4*)&Ks[j][half * 64 + 4 * i];
                part += q4[i].x * kv.x + q4[i].y * kv.y
                      + q4[i].z * kv.z + q4[i].w * kv.w;
            }
            float s = (part + __shfl_xor_sync(0xffffffffu, part, 1)) * scale;
            if (k0 + j > qrow) s = -1e30f;   // causal mask
            float mn   = fmaxf(m, s);
            float corr = __expf(m - mn);
            float p    = __expf(s - mn);
            l = l * corr + p;
#pragma unroll
            for (int i = 0; i < 16; i++) {
                float4 vv = *(const float4*)&Vs[j][half * 64 + 4 * i];
                acc[4 * i + 0] = acc[4 * i + 0] * corr + p * vv.x;
                acc[4 * i + 1] = acc[4 * i + 1] * corr + p * vv.y;
                acc[4 * i + 2] = acc[4 * i + 2] * corr + p * vv.z;
                acc[4 * i + 3] = acc[4 * i + 3] * corr + p * vv.w;
            }
            m = mn;
        }
    }

    float inv = 1.f / l;
    float* optr = O + base + (size_t)qrow * DIM + half * 64;
#pragma unroll
    for (int i = 0; i < 16; i++) {
        float4 o = make_float4(acc[4 * i] * inv, acc[4 * i + 1] * inv,
                               acc[4 * i + 2] * inv, acc[4 * i + 3] * inv);
        *(float4*)(optr + 4 * i) = o;
    }
}

// ---------------------------------------------------------------------------
extern "C" void kernel_launch(void* const* d_in, const int* in_sizes, int n_in,
                              void* d_out, int out_size) {
    const float* x  = (const float*)d_in[0];
    const float* wq = (const float*)d_in[1];
    const float* wk = (const float*)d_in[2];
    const float* wv = (const float*)d_in[3];
    const float* wo = (const float*)d_in[4];
    const float* fc = (const float*)d_in[5];
    const float* fs = (const float*)d_in[6];
    // d_in[7] = mask, unused (causal implemented directly)
    float* out = (float*)d_out;

    float *q, *k, *v, *ao;
    cudaGetSymbolAddress((void**)&q,  g_q);
    cudaGetSymbolAddress((void**)&k,  g_k);
    cudaGetSymbolAddress((void**)&v,  g_v);
    cudaGetSymbolAddress((void**)&ao, g_ao);

    dim3 ggrid(DIM / 128, M_TOT / 128);   // (16, 32)
    sgemm_nt<<<ggrid, 256>>>(x, wq, q);
    sgemm_nt<<<ggrid, 256>>>(x, wk, k);
    sgemm_nt<<<ggrid, 256>>>(x, wv, v);

    int np = M_TOT * DIM / 2;
    rope_kernel<<<(np + 255) / 256, 256>>>(q, k, fc, fs);

    dim3 fgrid(SEQ / BR, NH, BSZ);        // (16, 16, 2)
    flash_kernel<<<fgrid, 256>>>(q, k, v, ao);

    sgemm_nt<<<ggrid, 256>>>(ao, wo, out);
}

// round 5
// speedup vs baseline: 1.5506x; 1.5506x over previous
#include <cuda_runtime.h>
#include <cuda_bf16.h>
#include <cstdint>
#include <math.h>

#define BSZ 2
#define SEQ 2048
#define DIM 2048
#define NH 16
#define HD 128
#define M_TOT (BSZ * SEQ)   // 4096

// Scratch: Q, K, V activations and attention output (pre out-proj).
__device__ float g_q[(size_t)M_TOT * DIM];
__device__ float g_k[(size_t)M_TOT * DIM];
__device__ float g_v[(size_t)M_TOT * DIM];
__device__ float g_ao[(size_t)M_TOT * DIM];

// ===========================================================================
// Warp-MMA helpers (sm_80-baseline PTX: ldmatrix + mma.sync bf16 — these are
// NOT arch-variant ('a') gated, unlike tcgen05 which ptxas rejects at sm_103)
// ===========================================================================
__device__ __forceinline__ uint32_t smem_u32(const void* p) {
    uint32_t a;
    asm("{ .reg .u64 t; cvta.to.shared.u64 t, %1; cvt.u32.u64 %0, t; }" : "=r"(a) : "l"(p));
    return a;
}
__device__ __forceinline__ void ldsm_x4(uint32_t* r, uint32_t addr) {
    asm volatile("ldmatrix.sync.aligned.m8n8.x4.shared.b16 {%0,%1,%2,%3}, [%4];"
                 : "=r"(r[0]), "=r"(r[1]), "=r"(r[2]), "=r"(r[3]) : "r"(addr));
}
__device__ __forceinline__ void ldsm_x2(uint32_t* r, uint32_t addr) {
    asm volatile("ldmatrix.sync.aligned.m8n8.x2.shared.b16 {%0,%1}, [%2];"
                 : "=r"(r[0]), "=r"(r[1]) : "r"(addr));
}
__device__ __forceinline__ void mma16816(float* d, const uint32_t* a, const uint32_t* b) {
    asm volatile(
        "mma.sync.aligned.m16n8k16.row.col.f32.bf16.bf16.f32 "
        "{%0,%1,%2,%3}, {%4,%5,%6,%7}, {%8,%9}, {%0,%1,%2,%3};"
        : "+f"(d[0]), "+f"(d[1]), "+f"(d[2]), "+f"(d[3])
        : "r"(a[0]), "r"(a[1]), "r"(a[2]), "r"(a[3]), "r"(b[0]), "r"(b[1]));
}

// ===========================================================================
// GEMM: C[M,N] = A[M,K] @ B[N,K]^T, fp32 in/out, bf16 hi/lo split (3 passes).
// Block tile 128x128, 8 warps (2m x 4n), warp tile 64x32, K-chunk 32.
// Smem: padded row stride 40 bf16 (80B) -> conflict-free ldmatrix. 2 buffers.
// ===========================================================================
#define KC 32
#define ASTRIDE 40                      // bf16 elements per smem row
#define SM_TILE (128 * ASTRIDE)         // 5120 bf16 elems per (tile, hi|lo)
#define GEMM_SMEM (8 * SM_TILE * 2)     // A:4 tiles + B:4 tiles = 81920 B

__device__ __forceinline__ void split_store(__nv_bfloat16* hi, __nv_bfloat16* lo,
                                            int row, int c4, float4 v) {
    __nv_bfloat16 h0 = __float2bfloat16(v.x), h1 = __float2bfloat16(v.y);
    __nv_bfloat16 h2 = __float2bfloat16(v.z), h3 = __float2bfloat16(v.w);
    __nv_bfloat16 l0 = __float2bfloat16(v.x - __bfloat162float(h0));
    __nv_bfloat16 l1 = __float2bfloat16(v.y - __bfloat162float(h1));
    __nv_bfloat16 l2 = __float2bfloat16(v.z - __bfloat162float(h2));
    __nv_bfloat16 l3 = __float2bfloat16(v.w - __bfloat162float(h3));
    __nv_bfloat162 hp0 = __halves2bfloat162(h0, h1), hp1 = __halves2bfloat162(h2, h3);
    __nv_bfloat162 lp0 = __halves2bfloat162(l0, l1), lp1 = __halves2bfloat162(l2, l3);
    int e = row * ASTRIDE + c4 * 4;
    *(uint2*)(hi + e) = make_uint2(*(uint32_t*)&hp0, *(uint32_t*)&hp1);
    *(uint2*)(lo + e) = make_uint2(*(uint32_t*)&lp0, *(uint32_t*)&lp1);
}

__global__ __launch_bounds__(256) void gemm_mma(const float* __restrict__ A,
                                                const float* __restrict__ B,
                                                float* __restrict__ C) {
    extern __shared__ __nv_bfloat16 sm[];
    // layout (bf16 elems): A: [buf][hi|lo][SM_TILE] then B likewise
    __nv_bfloat16* sA = sm;
    __nv_bfloat16* sB = sm + 4 * SM_TILE;

    int t = threadIdx.x, lane = t & 31, warp = t >> 5;
    int wm = (warp & 1) * 64;           // warp m-offset in tile
    int wn = (warp >> 1) * 32;          // warp n-offset in tile
    int bm = blockIdx.y * 128, bn = blockIdx.x * 128;

    const float* Abase = A + (size_t)bm * DIM;
    const float* Bbase = B + (size_t)bn * DIM;

    // smem byte bases for ldmatrix
    uint32_t sAu = smem_u32(sA), sBu = smem_u32(sB);
    // per-thread invariant ldmatrix offsets (bytes)
    uint32_t aoff = (uint32_t)(((wm + (lane & 15)) * ASTRIDE + (lane >> 4) * 8) * 2);
    uint32_t boff = (uint32_t)(((wn + (lane & 7)) * ASTRIDE + ((lane >> 3) & 1) * 8) * 2);

    float acc[4][4][4];
#pragma unroll
    for (int i = 0; i < 4; i++)
#pragma unroll
        for (int j = 0; j < 4; j++)
#pragma unroll
            for (int r = 0; r < 4; r++) acc[i][j][r] = 0.f;

    const int NCHUNK = DIM / KC;        // 64
    float4 pa[4], pb[4];

    // prologue: chunk 0 -> buf 0
#pragma unroll
    for (int i = 0; i < 4; i++) {
        int f = t + 256 * i, row = f >> 3, c4 = f & 7;
        pa[i] = *(const float4*)(Abase + (size_t)row * DIM + c4 * 4);
        pb[i] = *(const float4*)(Bbase + (size_t)row * DIM + c4 * 4);
    }
#pragma unroll
    for (int i = 0; i < 4; i++) {
        int f = t + 256 * i, row = f >> 3, c4 = f & 7;
        split_store(sA, sA + SM_TILE, row, c4, pa[i]);
        split_store(sB, sB + SM_TILE, row, c4, pb[i]);
    }

    for (int c = 0; c < NCHUNK; c++) {
        // prefetch chunk c+1 (global -> regs), overlaps with MMAs below
        if (c + 1 < NCHUNK) {
            int k0 = (c + 1) * KC;
#pragma unroll
            for (int i = 0; i < 4; i++) {
                int f = t + 256 * i, row = f >> 3, c4 = f & 7;
                pa[i] = *(const float4*)(Abase + (size_t)row * DIM + k0 + c4 * 4);
                pb[i] = *(const float4*)(Bbase + (size_t)row * DIM + k0 + c4 * 4);
            }
        }
        __syncthreads();   // buf[c&1] fully stored; buf[(c+1)&1] readers done

        uint32_t aHi = sAu + (uint32_t)((c & 1) * 2 * SM_TILE * 2);
        uint32_t aLo = aHi + SM_TILE * 2;
        uint32_t bHi = sBu + (uint32_t)((c & 1) * 2 * SM_TILE * 2);
        uint32_t bLo = bHi + SM_TILE * 2;

#pragma unroll
        for (int ks = 0; ks < 2; ks++) {
            uint32_t kb = ks * 32;      // 16 bf16 = 32 bytes
            uint32_t a[4][4], bh[4][2], bl[4][2];
#pragma unroll
            for (int i = 0; i < 4; i++) ldsm_x4(a[i], aHi + aoff + i * (16 * ASTRIDE * 2) + kb);
#pragma unroll
            for (int j = 0; j < 4; j++) ldsm_x2(bh[j], bHi + boff + j * (8 * ASTRIDE * 2) + kb);
#pragma unroll
            for (int j = 0; j < 4; j++) ldsm_x2(bl[j], bLo + boff + j * (8 * ASTRIDE * 2) + kb);
#pragma unroll
            for (int i = 0; i < 4; i++)
#pragma unroll
                for (int j = 0; j < 4; j++) mma16816(acc[i][j], a[i], bh[j]);
#pragma unroll
            for (int i = 0; i < 4; i++)
#pragma unroll
                for (int j = 0; j < 4; j++) mma16816(acc[i][j], a[i], bl[j]);
#pragma unroll
            for (int i = 0; i < 4; i++) ldsm_x4(a[i], aLo + aoff + i * (16 * ASTRIDE * 2) + kb);
#pragma unroll
            for (int i = 0; i < 4; i++)
#pragma unroll
                for (int j = 0; j < 4; j++) mma16816(acc[i][j], a[i], bh[j]);
        }

        // stage chunk c+1 into the other buffer
        if (c + 1 < NCHUNK) {
            int buf = (c + 1) & 1;
            __nv_bfloat16* dAh = sA + buf * 2 * SM_TILE;
            __nv_bfloat16* dBh = sB + buf * 2 * SM_TILE;
#pragma unroll
            for (int i = 0; i < 4; i++) {
                int f = t + 256 * i, row = f >> 3, c4 = f & 7;
                split_store(dAh, dAh + SM_TILE, row, c4, pa[i]);
                split_store(dBh, dBh + SM_TILE, row, c4, pb[i]);
            }
        }
    }

    // epilogue: write accumulators
#pragma unroll
    for (int i = 0; i < 4; i++) {
        int r0 = bm + wm + i * 16 + (lane >> 2);
#pragma unroll
        for (int j = 0; j < 4; j++) {
            int c0 = bn + wn + j * 8 + (lane & 3) * 2;
            *(float2*)(C + (size_t)r0 * DIM + c0)       = make_float2(acc[i][j][0], acc[i][j][1]);
            *(float2*)(C + (size_t)(r0 + 8) * DIM + c0) = make_float2(acc[i][j][2], acc[i][j][3]);
        }
    }
}

// ---------------------------------------------------------------------------
// RoPE on Q and K in-place. Layout [M_TOT, DIM], pair (2i, 2i+1) within head.
// ---------------------------------------------------------------------------
__global__ void rope_kernel(float* __restrict__ q, float* __restrict__ k,
                            const float* __restrict__ cs, const float* __restrict__ sn) {
    int p = blockIdx.x * blockDim.x + threadIdx.x;
    const int NP = M_TOT * DIM / 2;
    if (p >= NP) return;
    int row = p / (DIM / 2);
    int pr  = p % (DIM / 2);
    int h = pr / (HD / 2);
    int i = pr % (HD / 2);
    int s = row % SEQ;
    float c  = cs[s * (HD / 2) + i];
    float si = sn[s * (HD / 2) + i];
    size_t off = (size_t)row * DIM + h * HD + 2 * i;
    float2 qv = *(float2*)(q + off);
    float2 kv = *(float2*)(k + off);
    *(float2*)(q + off) = make_float2(qv.x * c - qv.y * si, qv.x * si + qv.y * c);
    *(float2*)(k + off) = make_float2(kv.x * c - kv.y * si, kv.x * si + kv.y * c);
}

// ---------------------------------------------------------------------------
// Flash attention (fp32, causal), unchanged from R1.
// ---------------------------------------------------------------------------
#define BR 128
#define BC 64
__global__ __launch_bounds__(256) void flash_kernel(const float* __restrict__ Q,
                                                    const float* __restrict__ Kg,
                                                    const float* __restrict__ Vg,
                                                    float* __restrict__ O) {
    __shared__ float Ks[BC][HD];
    __shared__ float Vs[BC][HD];
    int b = blockIdx.z, h = blockIdx.y, q0 = blockIdx.x * BR;
    int t = threadIdx.x;
    int row = t >> 1, half = t & 1;
    int qrow = q0 + row;
    size_t base = (size_t)b * SEQ * DIM + (size_t)h * HD;

    float4 q4[16];
    const float* qptr = Q + base + (size_t)qrow * DIM + half * 64;
#pragma unroll
    for (int i = 0; i < 16; i++) q4[i] = *(const float4*)(qptr + 4 * i);

    float acc[64];
#pragma unroll
    for (int i = 0; i < 64; i++) acc[i] = 0.f;
    float m = -1e30f, l = 0.f;
    const float scale = 0.08838834764831845f;

    int nk = q0 / BC + 2;
    for (int kt = 0; kt < nk; kt++) {
        int k0 = kt * BC;
        __syncthreads();
#pragma unroll
        for (int i = 0; i < 8; i++) {
            int fl = t + 256 * i;
            int r  = fl >> 5;
            int c4 = fl & 31;
            size_t g = base + (size_t)(k0 + r) * DIM + c4 * 4;
            *(float4*)&Ks[r][c4 * 4] = *(const float4*)(Kg + g);
            *(float4*)&Vs[r][c4 * 4] = *(const float4*)(Vg + g);
        }
        __syncthreads();

        for (int j = 0; j < BC; j++) {
            float part = 0.f;
#pragma unroll
            for (int i = 0; i < 16; i++) {
                float4 kv = *(const float4*)&Ks[j][half * 64 + 4 * i];
                part += q4[i].x * kv.x + q4[i].y * kv.y + q4[i].z * kv.z + q4[i].w * kv.w;
            }
            float s = (part + __shfl_xor_sync(0xffffffffu, part, 1)) * scale;
            if (k0 + j > qrow) s = -1e30f;
            float mn   = fmaxf(m, s);
            float corr = __expf(m - mn);
            float p    = __expf(s - mn);
            l = l * corr + p;
#pragma unroll
            for (int i = 0; i < 16; i++) {
                float4 vv = *(const float4*)&Vs[j][half * 64 + 4 * i];
                acc[4 * i + 0] = acc[4 * i + 0] * corr + p * vv.x;
                acc[4 * i + 1] = acc[4 * i + 1] * corr + p * vv.y;
                acc[4 * i + 2] = acc[4 * i + 2] * corr + p * vv.z;
                acc[4 * i + 3] = acc[4 * i + 3] * corr + p * vv.w;
            }
            m = mn;
        }
    }

    float inv = 1.f / l;
    float* optr = O + base + (size_t)qrow * DIM + half * 64;
#pragma unroll
    for (int i = 0; i < 16; i++) {
        *(float4*)(optr + 4 * i) = make_float4(acc[4 * i] * inv, acc[4 * i + 1] * inv,
                                               acc[4 * i + 2] * inv, acc[4 * i + 3] * inv);
    }
}

// ---------------------------------------------------------------------------
extern "C" void kernel_launch(void* const* d_in, const int* in_sizes, int n_in,
                              void* d_out, int out_size) {
    const float* x  = (const float*)d_in[0];
    const float* wq = (const float*)d_in[1];
    const float* wk = (const float*)d_in[2];
    const float* wv = (const float*)d_in[3];
    const float* wo = (const float*)d_in[4];
    const float* fc = (const float*)d_in[5];
    const float* fs = (const float*)d_in[6];
    float* out = (float*)d_out;

    float *q, *k, *v, *ao;
    cudaGetSymbolAddress((void**)&q,  g_q);
    cudaGetSymbolAddress((void**)&k,  g_k);
    cudaGetSymbolAddress((void**)&v,  g_v);
    cudaGetSymbolAddress((void**)&ao, g_ao);

    cudaFuncSetAttribute(gemm_mma, cudaFuncAttributeMaxDynamicSharedMemorySize, GEMM_SMEM);

    dim3 ggrid(DIM / 128, M_TOT / 128);   // (16, 32)
    gemm_mma<<<ggrid, 256, GEMM_SMEM>>>(x, wq, q);
    gemm_mma<<<ggrid, 256, GEMM_SMEM>>>(x, wk, k);
    gemm_mma<<<ggrid, 256, GEMM_SMEM>>>(x, wv, v);

    int np = M_TOT * DIM / 2;
    rope_kernel<<<(np + 255) / 256, 256>>>(q, k, fc, fs);

    dim3 fgrid(SEQ / BR, NH, BSZ);        // (16, 16, 2)
    flash_kernel<<<fgrid, 256>>>(q, k, v, ao);

    gemm_mma<<<ggrid, 256, GEMM_SMEM>>>(ao, wo, out);
}

// round 6
// speedup vs baseline: 3.6343x; 2.3438x over previous
#include <cuda_runtime.h>
#include <cuda_bf16.h>
#include <cstdint>
#include <math.h>

#define BSZ 2
#define SEQ 2048
#define DIM 2048
#define NH 16
#define HD 128
#define M_TOT (BSZ * SEQ)   // 4096

typedef __nv_bfloat16 bf16;

// ---------------- scratch (device globals; no allocs allowed) ----------------
__device__ float g_q[(size_t)M_TOT * DIM];
__device__ float g_k[(size_t)M_TOT * DIM];
__device__ float g_v[(size_t)M_TOT * DIM];
__device__ bf16 g_xh[(size_t)M_TOT * DIM], g_xl[(size_t)M_TOT * DIM];
__device__ bf16 g_wh[(size_t)4 * DIM * DIM], g_wl[(size_t)4 * DIM * DIM];
__device__ bf16 g_qh[(size_t)M_TOT * DIM], g_ql[(size_t)M_TOT * DIM];
__device__ bf16 g_kh[(size_t)M_TOT * DIM], g_kl[(size_t)M_TOT * DIM];
__device__ bf16 g_vh[(size_t)M_TOT * DIM], g_vl[(size_t)M_TOT * DIM];
__device__ bf16 g_aoh[(size_t)M_TOT * DIM], g_aol[(size_t)M_TOT * DIM];

// ---------------- PTX helpers ----------------
__device__ __forceinline__ uint32_t smem_u32(const void* p) {
    uint32_t a;
    asm("{ .reg .u64 t; cvta.to.shared.u64 t, %1; cvt.u32.u64 %0, t; }" : "=r"(a) : "l"(p));
    return a;
}
__device__ __forceinline__ void ldsm_x4(uint32_t* r, uint32_t addr) {
    asm volatile("ldmatrix.sync.aligned.m8n8.x4.shared.b16 {%0,%1,%2,%3}, [%4];"
                 : "=r"(r[0]), "=r"(r[1]), "=r"(r[2]), "=r"(r[3]) : "r"(addr));
}
__device__ __forceinline__ void ldsm_x2(uint32_t* r, uint32_t addr) {
    asm volatile("ldmatrix.sync.aligned.m8n8.x2.shared.b16 {%0,%1}, [%2];"
                 : "=r"(r[0]), "=r"(r[1]) : "r"(addr));
}
__device__ __forceinline__ void ldsm_x2t(uint32_t* r, uint32_t addr) {
    asm volatile("ldmatrix.sync.aligned.m8n8.x2.trans.shared.b16 {%0,%1}, [%2];"
                 : "=r"(r[0]), "=r"(r[1]) : "r"(addr));
}
__device__ __forceinline__ void mma16816(float* d, const uint32_t* a, const uint32_t* b) {
    asm volatile(
        "mma.sync.aligned.m16n8k16.row.col.f32.bf16.bf16.f32 "
        "{%0,%1,%2,%3}, {%4,%5,%6,%7}, {%8,%9}, {%0,%1,%2,%3};"
        : "+f"(d[0]), "+f"(d[1]), "+f"(d[2]), "+f"(d[3])
        : "r"(a[0]), "r"(a[1]), "r"(a[2]), "r"(a[3]), "r"(b[0]), "r"(b[1]));
}
__device__ __forceinline__ void cp16(uint32_t dst, const void* src) {
    asm volatile("cp.async.cg.shared.global [%0], [%1], 16;" :: "r"(dst), "l"(src) : "memory");
}
#define CP_COMMIT() asm volatile("cp.async.commit_group;" ::: "memory")
#define CP_WAIT(n)  asm volatile("cp.async.wait_group %0;" :: "n"(n) : "memory")

// FFMA-only exp2 (x <= 0 path; degree-6 Taylor on [-0.5, 0.5], rel err ~3e-8)
__device__ __forceinline__ float exp2_fast(float x) {
    x = fmaxf(x, -125.f);
    float r = x + 12582912.f;                      // 1.5 * 2^23 round trick
    int  e = __float_as_int(r) - 0x4B400000;       // integer part
    float f = x - (r - 12582912.f);                // frac in [-0.5, 0.5]
    float p = 1.5403530e-4f;
    p = fmaf(p, f, 1.3333558e-3f);
    p = fmaf(p, f, 9.6181291e-3f);
    p = fmaf(p, f, 5.5504109e-2f);
    p = fmaf(p, f, 2.4022651e-1f);
    p = fmaf(p, f, 6.9314718e-1f);
    p = fmaf(p, f, 1.0f);
    return __int_as_float(__float_as_int(p) + (e << 23));
}

// split a pair of floats into packed bf16 hi + bf16 residual lo
__device__ __forceinline__ void split2(float a, float b, uint32_t& hi, uint32_t& lo) {
    bf16 ha = __float2bfloat16_rn(a), hb = __float2bfloat16_rn(b);
    float ra = a - __bfloat162float(ha), rb = b - __bfloat162float(hb);
    __nv_bfloat162 hp = __halves2bfloat162(ha, hb);
    __nv_bfloat162 lp = __floats2bfloat162_rn(ra, rb);
    hi = *(uint32_t*)&hp;
    lo = *(uint32_t*)&lp;
}

// ---------------- prep: fp32 -> bf16 hi/lo global buffers ----------------
__global__ void split_kernel(const float* __restrict__ src, bf16* __restrict__ hi,
                             bf16* __restrict__ lo, int n2) {
    int i = blockIdx.x * blockDim.x + threadIdx.x;
    if (i >= n2) return;
    float2 v = *(const float2*)(src + 2 * (size_t)i);
    uint32_t h, l;
    split2(v.x, v.y, h, l);
    *(uint32_t*)(hi + 2 * (size_t)i) = h;
    *(uint32_t*)(lo + 2 * (size_t)i) = l;
}

// ---------------- rope + convert q,k,v to hi/lo (q scaled by log2e/sqrt(HD)) --
#define SQ 0.127526015f   // log2(e) / sqrt(128)
__global__ void rope_cvt(const float* __restrict__ q, const float* __restrict__ k,
                         const float* __restrict__ v,
                         const float* __restrict__ cs, const float* __restrict__ sn,
                         bf16* qh, bf16* ql, bf16* kh, bf16* kl, bf16* vh, bf16* vl) {
    int p = blockIdx.x * blockDim.x + threadIdx.x;
    const int NP = M_TOT * DIM / 2;
    if (p >= NP) return;
    int row = p / (DIM / 2), pr = p % (DIM / 2);
    int hh = pr / (HD / 2), i = pr % (HD / 2);
    int s = row % SEQ;
    float c  = cs[s * (HD / 2) + i];
    float sn_ = sn[s * (HD / 2) + i];
    size_t off = (size_t)row * DIM + hh * HD + 2 * i;
    float2 qv = *(const float2*)(q + off);
    float2 kv = *(const float2*)(k + off);
    float2 vv = *(const float2*)(v + off);
    float q0 = (qv.x * c - qv.y * sn_) * SQ, q1 = (qv.x * sn_ + qv.y * c) * SQ;
    float k0 = kv.x * c - kv.y * sn_,        k1 = kv.x * sn_ + kv.y * c;
    uint32_t h, l;
    split2(q0, q1, h, l);   *(uint32_t*)(qh + off) = h; *(uint32_t*)(ql + off) = l;
    split2(k0, k1, h, l);   *(uint32_t*)(kh + off) = h; *(uint32_t*)(kl + off) = l;
    split2(vv.x, vv.y, h, l); *(uint32_t*)(vh + off) = h; *(uint32_t*)(vl + off) = l;
}

// ===========================================================================
// bf16 GEMM: C[M,N] = (Ah+Al)[M,K] @ (Bh+Bl)[N,K]^T, 3-pass split.
// Block 128x128, 8 warps 2x4, KC=64, 2-stage cp.async pipeline.
// grid.z selects B matrix (z*DIM*DIM offset) and C output.
// ===========================================================================
#define KC 64
#define ASTR 72                         // bf16 elems per smem row (144B, 16B-aligned)
#define GTILE (128 * ASTR)              // elems per (matrix, half) tile
#define STAGE_ELEMS (4 * GTILE)
#define GEMM_SMEM (2 * STAGE_ELEMS * 2) // 147456 bytes

__global__ __launch_bounds__(256) void gemm_bf16(
    const bf16* __restrict__ Ah, const bf16* __restrict__ Al,
    const bf16* __restrict__ Bh_all, const bf16* __restrict__ Bl_all,
    float* __restrict__ C0, float* __restrict__ C1, float* __restrict__ C2) {
    extern __shared__ bf16 sm[];
    int z = blockIdx.z;
    const bf16* Bh = Bh_all + (size_t)z * DIM * DIM;
    const bf16* Bl = Bl_all + (size_t)z * DIM * DIM;
    float* C = (z == 0) ? C0 : (z == 1) ? C1 : C2;

    int t = threadIdx.x, lane = t & 31, warp = t >> 5;
    int wm = (warp & 1) * 64, wn = (warp >> 1) * 32;
    int bm = blockIdx.y * 128, bn = blockIdx.x * 128;
    const bf16* Agh = Ah + (size_t)bm * DIM;
    const bf16* Agl = Al + (size_t)bm * DIM;
    const bf16* Bgh = Bh + (size_t)bn * DIM;
    const bf16* Bgl = Bl + (size_t)bn * DIM;
    uint32_t sb = smem_u32(sm);

    float acc[4][4][4];
#pragma unroll
    for (int i = 0; i < 4; i++)
#pragma unroll
        for (int j = 0; j < 4; j++)
#pragma unroll
            for (int r = 0; r < 4; r++) acc[i][j][r] = 0.f;

    const int NCH = DIM / KC;   // 32

    // stage loader: buffer order [Ah, Al, Bh, Bl], each 128 rows x 128B
#define STAGE_LOAD(S, CC)                                                        \
    {                                                                            \
        int k0_ = (CC) * KC;                                                     \
        uint32_t ds = sb + (uint32_t)((S) * STAGE_ELEMS) * 2;                    \
        _Pragma("unroll")                                                        \
        for (int i_ = 0; i_ < 4; i_++) {                                         \
            int li = t + 256 * i_;                                               \
            int rr = li >> 3, seg = li & 7;                                      \
            uint32_t so = (uint32_t)(rr * ASTR + seg * 8) * 2;                   \
            size_t go = (size_t)rr * DIM + k0_ + seg * 8;                        \
            cp16(ds + so,                      Agh + go);                        \
            cp16(ds + GTILE * 2 + so,          Agl + go);                        \
            cp16(ds + 2 * GTILE * 2 + so,      Bgh + go);                        \
            cp16(ds + 3 * GTILE * 2 + so,      Bgl + go);                        \
        }                                                                        \
    }

    STAGE_LOAD(0, 0);
    CP_COMMIT();

    for (int c = 0; c < NCH; c++) {
        int s = c & 1;
        if (c + 1 < NCH) {
            STAGE_LOAD(s ^ 1, c + 1);
            CP_COMMIT();
            CP_WAIT(1);
        } else {
            CP_WAIT(0);
        }
        __syncthreads();

        uint32_t Ab  = sb + (uint32_t)(s * STAGE_ELEMS) * 2;
        uint32_t Alb = Ab + GTILE * 2;
        uint32_t Bb  = Ab + 2 * GTILE * 2;
        uint32_t Blb = Ab + 3 * GTILE * 2;

#pragma unroll
        for (int ks = 0; ks < 4; ks++) {
            uint32_t ah[4][4], al[4][4], bh[4][2], bl[4][2];
#pragma unroll
            for (int i = 0; i < 4; i++) {
                uint32_t ao = (uint32_t)((wm + i * 16 + (lane & 15)) * ASTR + ks * 16 + (lane >> 4) * 8) * 2;
                ldsm_x4(ah[i], Ab + ao);
                ldsm_x4(al[i], Alb + ao);
            }
#pragma unroll
            for (int j = 0; j < 4; j++) {
                uint32_t bo = (uint32_t)((wn + j * 8 + (lane & 7)) * ASTR + ks * 16 + ((lane >> 3) & 1) * 8) * 2;
                ldsm_x2(bh[j], Bb + bo);
                ldsm_x2(bl[j], Blb + bo);
            }
#pragma unroll
            for (int i = 0; i < 4; i++)
#pragma unroll
                for (int j = 0; j < 4; j++) mma16816(acc[i][j], ah[i], bh[j]);
#pragma unroll
            for (int i = 0; i < 4; i++)
#pragma unroll
                for (int j = 0; j < 4; j++) mma16816(acc[i][j], ah[i], bl[j]);
#pragma unroll
            for (int i = 0; i < 4; i++)
#pragma unroll
                for (int j = 0; j < 4; j++) mma16816(acc[i][j], al[i], bh[j]);
        }
        __syncthreads();
    }

#pragma unroll
    for (int i = 0; i < 4; i++) {
        int r0 = bm + wm + i * 16 + (lane >> 2);
#pragma unroll
        for (int j = 0; j < 4; j++) {
            int c0 = bn + wn + j * 8 + (lane & 3) * 2;
            *(float2*)(C + (size_t)r0 * DIM + c0)       = make_float2(acc[i][j][0], acc[i][j][1]);
            *(float2*)(C + (size_t)(r0 + 8) * DIM + c0) = make_float2(acc[i][j][2], acc[i][j][3]);
        }
    }
}

// ===========================================================================
// Flash attention with mma.sync, hi/lo split for QK^T and PV. Causal.
// Block = (b, h, 128-q-rows); 8 warps, warp w owns rows 16w..16w+15.
// smem: Qh,Ql,Kh,Kl,Vh,Vl tiles 128x128 bf16, stride 136.
// ===========================================================================
#define FSTR 136
#define FT (128 * FSTR)                 // elems per tile
#define FLASH_SMEM (6 * FT * 2)         // 208896 bytes

__global__ __launch_bounds__(256) void flash_mma(
    const bf16* __restrict__ qh, const bf16* __restrict__ ql,
    const bf16* __restrict__ kh, const bf16* __restrict__ kl,
    const bf16* __restrict__ vh, const bf16* __restrict__ vl,
    bf16* __restrict__ aoh, bf16* __restrict__ aol) {
    extern __shared__ bf16 fs[];
    int t = threadIdx.x, lane = t & 31, warp = t >> 5;
    int qblk = gridDim.x - 1 - blockIdx.x;     // big blocks first
    int hh = blockIdx.y, b = blockIdx.z;
    int q0 = qblk * 128;
    size_t hb = (size_t)b * SEQ * DIM + (size_t)hh * HD;
    uint32_t sb = smem_u32(fs);
    uint32_t Qh_s = sb,            Ql_s = sb + FT * 2;
    uint32_t Kh_s = sb + 2 * FT * 2, Kl_s = sb + 3 * FT * 2;
    uint32_t Vh_s = sb + 4 * FT * 2, Vl_s = sb + 5 * FT * 2;

    // Q tiles (once)
#pragma unroll
    for (int i = 0; i < 8; i++) {
        int li = t + 256 * i;
        int r = li >> 4, seg = li & 15;
        size_t g = hb + (size_t)(q0 + r) * DIM + seg * 8;
        uint32_t so = (uint32_t)(r * FSTR + seg * 8) * 2;
        cp16(Qh_s + so, qh + g);
        cp16(Ql_s + so, ql + g);
    }
    CP_COMMIT();

    float accO[16][4];
#pragma unroll
    for (int j = 0; j < 16; j++)
#pragma unroll
        for (int r = 0; r < 4; r++) accO[j][r] = 0.f;
    float m0 = -1e30f, m1 = -1e30f, l0 = 0.f, l1 = 0.f;
    int rl0 = 16 * warp + (lane >> 2), rl1 = rl0 + 8;

    for (int kt = 0; kt <= qblk; kt++) {
        int k0 = kt * 128;
#pragma unroll
        for (int i = 0; i < 8; i++) {
            int li = t + 256 * i;
            int r = li >> 4, seg = li & 15;
            size_t g = hb + (size_t)(k0 + r) * DIM + seg * 8;
            uint32_t so = (uint32_t)(r * FSTR + seg * 8) * 2;
            cp16(Kh_s + so, kh + g);
            cp16(Kl_s + so, kl + g);
            cp16(Vh_s + so, vh + g);
            cp16(Vl_s + so, vl + g);
        }
        CP_COMMIT();
        CP_WAIT(0);
        __syncthreads();

        // ---- S = Q K^T (3-pass split); scores already in log2 domain ----
        float accS[16][4];
#pragma unroll
        for (int j = 0; j < 16; j++)
#pragma unroll
            for (int r = 0; r < 4; r++) accS[j][r] = 0.f;

#pragma unroll
        for (int ks = 0; ks < 8; ks++) {
            uint32_t qf_h[4], qf_l[4];
            uint32_t ao = (uint32_t)((16 * warp + (lane & 15)) * FSTR + ks * 16 + (lane >> 4) * 8) * 2;
            ldsm_x4(qf_h, Qh_s + ao);
            ldsm_x4(qf_l, Ql_s + ao);
#pragma unroll
            for (int j = 0; j < 16; j++) {
                uint32_t bo = (uint32_t)((8 * j + (lane & 7)) * FSTR + ks * 16 + ((lane >> 3) & 1) * 8) * 2;
                uint32_t kf[2], kf2[2];
                ldsm_x2(kf, Kh_s + bo);
                mma16816(accS[j], qf_h, kf);
                mma16816(accS[j], qf_l, kf);
                ldsm_x2(kf2, Kl_s + bo);
                mma16816(accS[j], qf_h, kf2);
            }
        }

        // ---- causal mask on diagonal tile ----
        if (kt == qblk) {
            int cb = 2 * (lane & 3);
#pragma unroll
            for (int j = 0; j < 16; j++) {
                int c0 = 8 * j + cb;
                if (c0 > rl0)     accS[j][0] = -1e30f;
                if (c0 + 1 > rl0) accS[j][1] = -1e30f;
                if (c0 > rl1)     accS[j][2] = -1e30f;
                if (c0 + 1 > rl1) accS[j][3] = -1e30f;
            }
        }

        // ---- online softmax (base-2) ----
        float mx0 = -1e30f, mx1 = -1e30f;
#pragma unroll
        for (int j = 0; j < 16; j++) {
            mx0 = fmaxf(mx0, fmaxf(accS[j][0], accS[j][1]));
            mx1 = fmaxf(mx1, fmaxf(accS[j][2], accS[j][3]));
        }
        mx0 = fmaxf(mx0, __shfl_xor_sync(0xffffffffu, mx0, 1));
        mx0 = fmaxf(mx0, __shfl_xor_sync(0xffffffffu, mx0, 2));
        mx1 = fmaxf(mx1, __shfl_xor_sync(0xffffffffu, mx1, 1));
        mx1 = fmaxf(mx1, __shfl_xor_sync(0xffffffffu, mx1, 2));
        float mn0 = fmaxf(m0, mx0), mn1 = fmaxf(m1, mx1);
        float cr0 = exp2_fast(m0 - mn0), cr1 = exp2_fast(m1 - mn1);
        float s0 = 0.f, s1 = 0.f;
#pragma unroll
        for (int j = 0; j < 16; j++) {
            accS[j][0] = exp2_fast(accS[j][0] - mn0); s0 += accS[j][0];
            accS[j][1] = exp2_fast(accS[j][1] - mn0); s0 += accS[j][1];
            accS[j][2] = exp2_fast(accS[j][2] - mn1); s1 += accS[j][2];
            accS[j][3] = exp2_fast(accS[j][3] - mn1); s1 += accS[j][3];
        }
        s0 += __shfl_xor_sync(0xffffffffu, s0, 1);
        s0 += __shfl_xor_sync(0xffffffffu, s0, 2);
        s1 += __shfl_xor_sync(0xffffffffu, s1, 1);
        s1 += __shfl_xor_sync(0xffffffffu, s1, 2);
        l0 = l0 * cr0 + s0;
        l1 = l1 * cr1 + s1;
        m0 = mn0; m1 = mn1;
#pragma unroll
        for (int j = 0; j < 16; j++) {
            accO[j][0] *= cr0; accO[j][1] *= cr0;
            accO[j][2] *= cr1; accO[j][3] *= cr1;
        }

        // ---- O += P V (3-pass split; P split computed in-register) ----
#pragma unroll
        for (int ks = 0; ks < 8; ks++) {
            int ja = 2 * ks, jb = 2 * ks + 1;
            uint32_t ph[4], pl[4];
            split2(accS[ja][0], accS[ja][1], ph[0], pl[0]);
            split2(accS[ja][2], accS[ja][3], ph[1], pl[1]);
            split2(accS[jb][0], accS[jb][1], ph[2], pl[2]);
            split2(accS[jb][2], accS[jb][3], ph[3], pl[3]);
#pragma unroll
            for (int j2 = 0; j2 < 16; j2++) {
                uint32_t vo = (uint32_t)((16 * ks + (lane & 15)) * FSTR + 8 * j2) * 2;
                uint32_t vf[2], vf2[2];
                ldsm_x2t(vf, Vh_s + vo);
                mma16816(accO[j2], ph, vf);
                mma16816(accO[j2], pl, vf);
                ldsm_x2t(vf2, Vl_s + vo);
                mma16816(accO[j2], ph, vf2);
            }
        }
        __syncthreads();   // protect K/V smem before next tile's cp.async
    }

    // ---- epilogue: normalize, split to bf16 hi/lo, store ----
    float i0 = 1.f / l0, i1 = 1.f / l1;
#pragma unroll
    for (int j2 = 0; j2 < 16; j2++) {
        int col = 8 * j2 + 2 * (lane & 3);
        size_t o0 = hb + (size_t)(q0 + rl0) * DIM + col;
        size_t o1 = hb + (size_t)(q0 + rl1) * DIM + col;
        uint32_t h, l;
        split2(accO[j2][0] * i0, accO[j2][1] * i0, h, l);
        *(uint32_t*)(aoh + o0) = h; *(uint32_t*)(aol + o0) = l;
        split2(accO[j2][2] * i1, accO[j2][3] * i1, h, l);
        *(uint32_t*)(aoh + o1) = h; *(uint32_t*)(aol + o1) = l;
    }
}

// ---------------------------------------------------------------------------
extern "C" void kernel_launch(void* const* d_in, const int* in_sizes, int n_in,
                              void* d_out, int out_size) {
    const float* x  = (const float*)d_in[0];
    const float* wq = (const float*)d_in[1];
    const float* wk = (const float*)d_in[2];
    const float* wv = (const float*)d_in[3];
    const float* wo = (const float*)d_in[4];
    const float* fc = (const float*)d_in[5];
    const float* fs = (const float*)d_in[6];
    float* out = (float*)d_out;

    float *q, *k, *v;
    bf16 *xh, *xl, *wh, *wl, *qhp, *qlp, *khp, *klp, *vhp, *vlp, *aoh, *aol;
    cudaGetSymbolAddress((void**)&q,   g_q);
    cudaGetSymbolAddress((void**)&k,   g_k);
    cudaGetSymbolAddress((void**)&v,   g_v);
    cudaGetSymbolAddress((void**)&xh,  g_xh);
    cudaGetSymbolAddress((void**)&xl,  g_xl);
    cudaGetSymbolAddress((void**)&wh,  g_wh);
    cudaGetSymbolAddress((void**)&wl,  g_wl);
    cudaGetSymbolAddress((void**)&qhp, g_qh);
    cudaGetSymbolAddress((void**)&qlp, g_ql);
    cudaGetSymbolAddress((void**)&khp, g_kh);
    cudaGetSymbolAddress((void**)&klp, g_kl);
    cudaGetSymbolAddress((void**)&vhp, g_vh);
    cudaGetSymbolAddress((void**)&vlp, g_vl);
    cudaGetSymbolAddress((void**)&aoh, g_aoh);
    cudaGetSymbolAddress((void**)&aol, g_aol);

    cudaFuncSetAttribute(gemm_bf16, cudaFuncAttributeMaxDynamicSharedMemorySize, GEMM_SMEM);
    cudaFuncSetAttribute(flash_mma, cudaFuncAttributeMaxDynamicSharedMemorySize, FLASH_SMEM);

    // 1. split x and weights to bf16 hi/lo
    int nx2 = M_TOT * DIM / 2;
    int nw2 = DIM * DIM / 2;
    split_kernel<<<(nx2 + 255) / 256, 256>>>(x, xh, xl, nx2);
    split_kernel<<<(nw2 + 255) / 256, 256>>>(wq, wh,                          wl,                          nw2);
    split_kernel<<<(nw2 + 255) / 256, 256>>>(wk, wh + (size_t)1 * DIM * DIM,  wl + (size_t)1 * DIM * DIM,  nw2);
    split_kernel<<<(nw2 + 255) / 256, 256>>>(wv, wh + (size_t)2 * DIM * DIM,  wl + (size_t)2 * DIM * DIM,  nw2);
    split_kernel<<<(nw2 + 255) / 256, 256>>>(wo, wh + (size_t)3 * DIM * DIM,  wl + (size_t)3 * DIM * DIM,  nw2);

    // 2. fused QKV projections
    dim3 ggrid(DIM / 128, M_TOT / 128, 3);
    gemm_bf16<<<ggrid, 256, GEMM_SMEM>>>(xh, xl, wh, wl, q, k, v);

    // 3. rope + convert to hi/lo
    int np = M_TOT * DIM / 2;
    rope_cvt<<<(np + 255) / 256, 256>>>(q, k, v, fc, fs, qhp, qlp, khp, klp, vhp, vlp);

    // 4. flash attention (tensor cores)
    dim3 fgrid(SEQ / 128, NH, BSZ);
    flash_mma<<<fgrid, 256, FLASH_SMEM>>>(qhp, qlp, khp, klp, vhp, vlp, aoh, aol);

    // 5. output projection
    dim3 ogrid(DIM / 128, M_TOT / 128, 1);
    gemm_bf16<<<ogrid, 256, GEMM_SMEM>>>(aoh, aol, wh + (size_t)3 * DIM * DIM,
                                         wl + (size_t)3 * DIM * DIM, out, out, out);
}